// round 1
// baseline (speedup 1.0000x reference)
#include <cuda_runtime.h>
#include <cuda_bf16.h>

#define BB   16
#define CC   192
#define TXN  1024
#define MAXY 4096

// Scratch: token index per output frame (-1 = no token -> z = noise)
__device__ int g_idx[BB * MAXY];

// One block per batch. 1024 threads = TXN.
// Computes w = ceil(exp(logw)) masked by x_len, inclusive int prefix scan,
// scatters token id into g_idx band [cum-w, cum), writes y_mask.
__global__ void build_map_kernel(const float* __restrict__ logw,
                                 const int* __restrict__ x_lengths,
                                 float* __restrict__ y_mask_out) {
    __shared__ int s[TXN];
    const int b = blockIdx.x;
    const int t = threadIdx.x;

    const int xlen = max(x_lengths[b], 1);
    int w = 0;
    if (t < xlen) {
        w = (int)ceilf(expf(logw[b * TXN + t]));
    }
    s[t] = w;

    // init idx map to -1 (global, per-batch region)
    for (int ty = t; ty < MAXY; ty += TXN) g_idx[b * MAXY + ty] = -1;
    __syncthreads();

    // Hillis-Steele inclusive scan over TXN ints (exact: small integers)
    #pragma unroll
    for (int off = 1; off < TXN; off <<= 1) {
        int add = (t >= off) ? s[t - off] : 0;
        __syncthreads();
        s[t] += add;
        __syncthreads();
    }

    const int cum   = s[t];
    const int total = s[TXN - 1];
    const int ylen  = min(max(total, 1), MAXY);

    // scatter: frames [cum-w, cum) belong to token t
    const int start = cum - w;
    const int end   = min(cum, MAXY);
    for (int ty = start; ty < end; ty++) g_idx[b * MAXY + ty] = t;

    // y_mask
    if (y_mask_out != nullptr) {
        for (int ty = t; ty < MAXY; ty += TXN)
            y_mask_out[b * MAXY + ty] = (ty < ylen) ? 1.0f : 0.0f;
    }
}

// Expand: z[b,c,ty] = idx>=0 ? m_p[b,c,t] + noise[b,c,ty]*exp(logs_p[b,c,t])
//                            : noise[b,c,ty]
// float4-vectorized along ty. Memory-bound (~130 MB total traffic).
__global__ void expand_kernel(const float* __restrict__ m_p,
                              const float* __restrict__ logs_p,
                              const float* __restrict__ noise,
                              float* __restrict__ z) {
    const int nvec = BB * CC * MAXY / 4;
    int i = blockIdx.x * blockDim.x + threadIdx.x;
    if (i >= nvec) return;

    const int tyv = i % (MAXY / 4);      // vector index along ty
    const int bc  = i / (MAXY / 4);      // fused (b, c)
    const int b   = bc / CC;

    float4 nz = reinterpret_cast<const float4*>(noise)[i];
    const int* __restrict__ idx = g_idx + b * MAXY + tyv * 4;
    const float* __restrict__ mrow = m_p + (size_t)bc * TXN;
    const float* __restrict__ srow = logs_p + (size_t)bc * TXN;

    float nv[4] = {nz.x, nz.y, nz.z, nz.w};
    float ov[4];
    #pragma unroll
    for (int k = 0; k < 4; k++) {
        int t = idx[k];
        float n = nv[k];
        ov[k] = (t >= 0) ? (mrow[t] + n * expf(srow[t])) : n;
    }
    float4 o = {ov[0], ov[1], ov[2], ov[3]};
    reinterpret_cast<float4*>(z)[i] = o;
}

extern "C" void kernel_launch(void* const* d_in, const int* in_sizes, int n_in,
                              void* d_out, int out_size) {
    const float* m_p    = (const float*)d_in[0];
    const float* logs_p = (const float*)d_in[1];
    const float* logw   = (const float*)d_in[2];
    const float* noise  = (const float*)d_in[3];
    const int*   xlens  = (const int*)d_in[4];

    float* out = (float*)d_out;
    const int zsize = BB * CC * MAXY;            // 12,582,912
    float* z = out;
    float* y_mask = (out_size >= zsize + BB * MAXY) ? (out + zsize) : nullptr;

    build_map_kernel<<<BB, TXN>>>(logw, xlens, y_mask);

    const int nvec = zsize / 4;                  // 3,145,728
    const int threads = 256;
    expand_kernel<<<(nvec + threads - 1) / threads, threads>>>(m_p, logs_p, noise, z);
}

// round 2
// speedup vs baseline: 1.0761x; 1.0761x over previous
#include <cuda_runtime.h>
#include <cuda_bf16.h>

#define BB   16
#define CC   192
#define TXN  1024
#define MAXY 4096

// Scratch: token index per output frame (-1 = no token -> z = noise)
__device__ int g_idx[BB * MAXY];

// One block per batch, 1024 threads.
// w = ceil(exp(logw)) masked by x_len; shfl-based inclusive scan;
// scatter token id into band [cum-w, cum); -1 tail; y_mask.
__global__ void build_map_kernel(const float* __restrict__ logw,
                                 const int* __restrict__ x_lengths,
                                 float* __restrict__ y_mask_out) {
    __shared__ int warp_sums[32];
    const int b    = blockIdx.x;
    const int t    = threadIdx.x;
    const int lane = t & 31;
    const int wid  = t >> 5;

    const int xlen = max(x_lengths[b], 1);
    int w = 0;
    if (t < xlen) {
        // accurate expf: feeds ceil(), ulp flips at integer boundaries matter
        w = (int)ceilf(expf(logw[b * TXN + t]));
    }

    // warp-level inclusive scan
    int c = w;
    #pragma unroll
    for (int o = 1; o < 32; o <<= 1) {
        int v = __shfl_up_sync(0xffffffffu, c, o);
        if (lane >= o) c += v;
    }
    if (lane == 31) warp_sums[wid] = c;
    __syncthreads();
    if (wid == 0) {
        int v = warp_sums[lane];
        #pragma unroll
        for (int o = 1; o < 32; o <<= 1) {
            int u = __shfl_up_sync(0xffffffffu, v, o);
            if (lane >= o) v += u;
        }
        warp_sums[lane] = v;
    }
    __syncthreads();

    const int base  = (wid > 0) ? warp_sums[wid - 1] : 0;
    const int cum   = base + c;               // inclusive prefix sum
    const int total = warp_sums[31];
    const int ylen  = min(max(total, 1), MAXY);

    int* __restrict__ row = g_idx + b * MAXY;

    // band scatter: frames [cum-w, cum) belong to token t
    const int end = min(cum, MAXY);
    for (int ty = cum - w; ty < end; ty++) row[ty] = t;

    // tail fill: frames beyond total have no token
    const int tail0 = min(total, MAXY);
    for (int ty = tail0 + t; ty < MAXY; ty += TXN) row[ty] = -1;

    // y_mask, one float4 per thread
    if (y_mask_out != nullptr) {
        const int v0 = t * 4;
        float4 m;
        m.x = (v0 + 0 < ylen) ? 1.0f : 0.0f;
        m.y = (v0 + 1 < ylen) ? 1.0f : 0.0f;
        m.z = (v0 + 2 < ylen) ? 1.0f : 0.0f;
        m.w = (v0 + 3 < ylen) ? 1.0f : 0.0f;
        reinterpret_cast<float4*>(y_mask_out + b * MAXY)[t] = m;
    }
}

// One block per (b,c) row. 256 threads x 4 float4 = 4096 ty per row.
// Front-load all independent loads (4 noise float4 + 4 idx int4) to maximize
// MLP before the dependent gathers; gathers hit the 8KB hot m/s row in L1.
__global__ void __launch_bounds__(256)
expand_kernel(const float* __restrict__ m_p,
              const float* __restrict__ logs_p,
              const float* __restrict__ noise,
              float* __restrict__ z) {
    const int bc  = blockIdx.x;      // 0..BB*CC-1
    const int b   = bc / CC;
    const int tid = threadIdx.x;

    const float4* __restrict__ nz4 = reinterpret_cast<const float4*>(noise) + (size_t)bc * (MAXY / 4);
    float4*       __restrict__ z4  = reinterpret_cast<float4*>(z)           + (size_t)bc * (MAXY / 4);
    const int4*   __restrict__ ix4 = reinterpret_cast<const int4*>(g_idx)   + b * (MAXY / 4);
    const float*  __restrict__ mrow = m_p    + (size_t)bc * TXN;
    const float*  __restrict__ srow = logs_p + (size_t)bc * TXN;

    float4 n[4];
    int4   ix[4];
    #pragma unroll
    for (int j = 0; j < 4; j++) n[j] = nz4[tid + j * 256];
    #pragma unroll
    for (int j = 0; j < 4; j++) ix[j] = ix4[tid + j * 256];

    #pragma unroll
    for (int j = 0; j < 4; j++) {
        const int   tt[4] = {ix[j].x, ix[j].y, ix[j].z, ix[j].w};
        const float nv[4] = {n[j].x, n[j].y, n[j].z, n[j].w};
        float ov[4];
        #pragma unroll
        for (int k = 0; k < 4; k++) {
            const int t = tt[k];
            // fast exp: error ~5e-7 rel, smooth perturbation only
            ov[k] = (t >= 0) ? fmaf(nv[k], __expf(srow[t]), mrow[t]) : nv[k];
        }
        z4[tid + j * 256] = make_float4(ov[0], ov[1], ov[2], ov[3]);
    }
}

extern "C" void kernel_launch(void* const* d_in, const int* in_sizes, int n_in,
                              void* d_out, int out_size) {
    const float* m_p    = (const float*)d_in[0];
    const float* logs_p = (const float*)d_in[1];
    const float* logw   = (const float*)d_in[2];
    const float* noise  = (const float*)d_in[3];
    const int*   xlens  = (const int*)d_in[4];

    float* out = (float*)d_out;
    const int zsize = BB * CC * MAXY;            // 12,582,912
    float* z = out;
    float* y_mask = (out_size >= zsize + BB * MAXY) ? (out + zsize) : nullptr;

    build_map_kernel<<<BB, TXN>>>(logw, xlens, y_mask);
    expand_kernel<<<BB * CC, 256>>>(m_p, logs_p, noise, z);
}

// round 3
// speedup vs baseline: 1.5497x; 1.4401x over previous
#include <cuda_runtime.h>
#include <cuda_bf16.h>

#define BB   16
#define CC   192
#define TXN  1024
#define MAXY 4096

// Scratch: token index per output frame (-1 = no token -> z = noise)
__device__ int g_idx[BB * MAXY];

// One block per batch, 1024 threads.
__global__ void build_map_kernel(const float* __restrict__ logw,
                                 const int* __restrict__ x_lengths,
                                 float* __restrict__ y_mask_out) {
    __shared__ int warp_sums[32];
    const int b    = blockIdx.x;
    const int t    = threadIdx.x;
    const int lane = t & 31;
    const int wid  = t >> 5;

    const int xlen = max(x_lengths[b], 1);
    int w = 0;
    if (t < xlen) {
        // accurate expf: feeds ceil(), ulp flips at integer boundaries matter
        w = (int)ceilf(expf(logw[b * TXN + t]));
    }

    // warp-level inclusive scan
    int c = w;
    #pragma unroll
    for (int o = 1; o < 32; o <<= 1) {
        int v = __shfl_up_sync(0xffffffffu, c, o);
        if (lane >= o) c += v;
    }
    if (lane == 31) warp_sums[wid] = c;
    __syncthreads();
    if (wid == 0) {
        int v = warp_sums[lane];
        #pragma unroll
        for (int o = 1; o < 32; o <<= 1) {
            int u = __shfl_up_sync(0xffffffffu, v, o);
            if (lane >= o) v += u;
        }
        warp_sums[lane] = v;
    }
    __syncthreads();

    const int base  = (wid > 0) ? warp_sums[wid - 1] : 0;
    const int cum   = base + c;               // inclusive prefix sum
    const int total = warp_sums[31];
    const int ylen  = min(max(total, 1), MAXY);

    int* __restrict__ row = g_idx + b * MAXY;

    // band scatter: frames [cum-w, cum) belong to token t
    const int end = min(cum, MAXY);
    for (int ty = cum - w; ty < end; ty++) row[ty] = t;

    // tail fill: frames beyond total have no token
    const int tail0 = min(total, MAXY);
    for (int ty = tail0 + t; ty < MAXY; ty += TXN) row[ty] = -1;

    // y_mask, one float4 per thread
    if (y_mask_out != nullptr) {
        const int v0 = t * 4;
        float4 m;
        m.x = (v0 + 0 < ylen) ? 1.0f : 0.0f;
        m.y = (v0 + 1 < ylen) ? 1.0f : 0.0f;
        m.z = (v0 + 2 < ylen) ? 1.0f : 0.0f;
        m.w = (v0 + 3 < ylen) ? 1.0f : 0.0f;
        reinterpret_cast<float4*>(y_mask_out + b * MAXY)[t] = m;
    }
}

// One block per (b,c) row, 256 threads x 4 float4 = 4096 ty.
// All global loads (noise, idx, m-row, s-row) issue before ONE barrier;
// gathers become LDS from the smem-staged row (broadcast-friendly).
// Streaming hints keep the 100MB noise/z stream out of L2's way.
__global__ void __launch_bounds__(256)
expand_kernel(const float* __restrict__ m_p,
              const float* __restrict__ logs_p,
              const float* __restrict__ noise,
              float* __restrict__ z) {
    __shared__ float sm[TXN];
    __shared__ float ss[TXN];

    const int bc  = blockIdx.x;      // 0..BB*CC-1
    const int b   = bc / CC;
    const int tid = threadIdx.x;

    const float4* __restrict__ nz4 = reinterpret_cast<const float4*>(noise) + (size_t)bc * (MAXY / 4);
    float4*       __restrict__ z4  = reinterpret_cast<float4*>(z)           + (size_t)bc * (MAXY / 4);
    const int4*   __restrict__ ix4 = reinterpret_cast<const int4*>(g_idx)   + b * (MAXY / 4);
    const float4* __restrict__ m4  = reinterpret_cast<const float4*>(m_p    + (size_t)bc * TXN);
    const float4* __restrict__ s4  = reinterpret_cast<const float4*>(logs_p + (size_t)bc * TXN);

    // ---- issue ALL global loads up front (10 independent LDG.128 / thread) ----
    float4 mv = m4[tid];             // coalesced row fill for smem
    float4 sv = s4[tid];

    float4 n[4];
    int4   ix[4];
    #pragma unroll
    for (int j = 0; j < 4; j++) n[j] = __ldcs(&nz4[tid + j * 256]);   // streamed once
    #pragma unroll
    for (int j = 0; j < 4; j++) ix[j] = ix4[tid + j * 256];

    reinterpret_cast<float4*>(sm)[tid] = mv;
    reinterpret_cast<float4*>(ss)[tid] = sv;
    __syncthreads();

    // ---- compute: LDS gathers (29cy, mostly broadcast), MUFU exp, FMA ----
    #pragma unroll
    for (int j = 0; j < 4; j++) {
        const int   tt[4] = {ix[j].x, ix[j].y, ix[j].z, ix[j].w};
        const float nv[4] = {n[j].x, n[j].y, n[j].z, n[j].w};
        float ov[4];
        #pragma unroll
        for (int k = 0; k < 4; k++) {
            const int t = tt[k];
            ov[k] = (t >= 0) ? fmaf(nv[k], __expf(ss[t]), sm[t]) : nv[k];
        }
        __stcs(&z4[tid + j * 256], make_float4(ov[0], ov[1], ov[2], ov[3]));
    }
}

extern "C" void kernel_launch(void* const* d_in, const int* in_sizes, int n_in,
                              void* d_out, int out_size) {
    const float* m_p    = (const float*)d_in[0];
    const float* logs_p = (const float*)d_in[1];
    const float* logw   = (const float*)d_in[2];
    const float* noise  = (const float*)d_in[3];
    const int*   xlens  = (const int*)d_in[4];

    float* out = (float*)d_out;
    const int zsize = BB * CC * MAXY;            // 12,582,912
    float* z = out;
    float* y_mask = (out_size >= zsize + BB * MAXY) ? (out + zsize) : nullptr;

    build_map_kernel<<<BB, TXN>>>(logw, xlens, y_mask);
    expand_kernel<<<BB * CC, 256>>>(m_p, logs_p, noise, z);
}